// round 1
// baseline (speedup 1.0000x reference)
#include <cuda_runtime.h>
#include <math.h>

#define BN_EPS 1e-5f

// ---------------- scratch (device globals; no allocation allowed) ----------------
__device__ float g_pool[8 * 64 * 32 * 32];     // 2 MB  pooled conv1 output
__device__ float g_nodes0[8192 * 128];         // 4 MB  node features after conv2
__device__ float g_h1[8192 * 256];             // 8 MB  GAT1 h = x @ W1
__device__ float g_x1[8192 * 256];             // 8 MB  relu(GAT1 out)
__device__ float g_h2[8192 * 128];             // 4 MB  GAT2 h
__device__ float g_x2[8192 * 128];             // 4 MB  relu(GAT2 out)
__device__ float g_s[1024];
__device__ float g_d[1024];

// ---------------- conv1 + bias + BN + ReLU + 2x2 maxpool ----------------
__global__ __launch_bounds__(256) void conv1_pool_kernel(
    const float* __restrict__ img, const float* __restrict__ w,
    const float* __restrict__ cb, const float* __restrict__ g,
    const float* __restrict__ bb, const float* __restrict__ m,
    const float* __restrict__ v)
{
    __shared__ float ws[1728];
    __shared__ float sc_s[64], sh_s[64];
    int t = threadIdx.x;
    for (int i = t; i < 1728; i += 256) ws[i] = w[i];
    if (t < 64) {
        float sc = g[t] * rsqrtf(v[t] + BN_EPS);
        sc_s[t] = sc;
        sh_s[t] = bb[t] - m[t] * sc + cb[t] * sc;   // fold conv bias into BN shift
    }
    __syncthreads();

    int idx = blockIdx.x * 256 + t;                 // 8*64*32*32 total
    int pw = idx & 31;
    int ph = (idx >> 5) & 31;
    int c  = (idx >> 10) & 63;
    int b  = idx >> 16;

    float win[3][4][4];
    int h0 = 2 * ph - 1, w0 = 2 * pw - 1;
#pragma unroll
    for (int ic = 0; ic < 3; ic++) {
        const float* ip = img + (b * 3 + ic) * 4096;
#pragma unroll
        for (int r = 0; r < 4; r++) {
            int ih = h0 + r;
            bool rok = (unsigned)ih < 64u;
#pragma unroll
            for (int cc = 0; cc < 4; cc++) {
                int iw = w0 + cc;
                win[ic][r][cc] = (rok && (unsigned)iw < 64u) ? ip[ih * 64 + iw] : 0.0f;
            }
        }
    }
    const float* wc = ws + c * 27;
    float sc = sc_s[c], sh = sh_s[c];
    float mx = 0.0f;                                // relu outputs >= 0
#pragma unroll
    for (int dh = 0; dh < 2; dh++)
#pragma unroll
    for (int dw = 0; dw < 2; dw++) {
        float s = 0.f;
#pragma unroll
        for (int ic = 0; ic < 3; ic++)
#pragma unroll
        for (int kh = 0; kh < 3; kh++)
#pragma unroll
        for (int kw = 0; kw < 3; kw++)
            s += win[ic][dh + kh][dw + kw] * wc[ic * 9 + kh * 3 + kw];
        float y = s * sc + sh;
        y = y > 0.f ? y : 0.f;
        mx = fmaxf(mx, y);
    }
    g_pool[idx] = mx;
}

// ---------------- conv2 + bias + BN + ReLU -> node-major [8192,128] ----------------
// grid: (4 chan-groups of 32, 32 rows, 8 images), 128 threads (32 px x 4 chan-octets)
// smem: input tile 64ch x 3rows x 34cols (6528 f) + weights 576x36 padded (20736 f)
__global__ __launch_bounds__(128) void conv2_kernel(
    const float* __restrict__ w2, const float* __restrict__ cb,
    const float* __restrict__ g, const float* __restrict__ bb,
    const float* __restrict__ m, const float* __restrict__ v)
{
    extern __shared__ float smem[];
    float* in_s = smem;            // 6528
    float* w_s  = smem + 6528;     // 20736

    int cg = blockIdx.x;           // 0..3
    int h  = blockIdx.y;           // 0..31
    int b  = blockIdx.z;           // 0..7
    int t  = threadIdx.x;

    for (int i = t; i < 6528; i += 128) {
        int col = i % 34;
        int kr  = (i / 34) % 3;
        int ic  = i / 102;
        int r = h + kr - 1;
        int wcol = col - 1;
        float val = 0.f;
        if ((unsigned)r < 32u && (unsigned)wcol < 32u)
            val = g_pool[((b * 64 + ic) * 32 + r) * 32 + wcol];
        in_s[i] = val;
    }
    const float* wg = w2 + cg * 32 * 576;
    for (int i = t; i < 18432; i += 128) {
        int cl  = i / 576;
        int rem = i - cl * 576;                    // ic*9 + kh*3 + kw
        w_s[rem * 36 + cl] = wg[i];
    }
    __syncthreads();

    int px = t & 31;
    int co = t >> 5;                                // 0..3 -> 8 channels each
    float acc[8] = {0.f, 0.f, 0.f, 0.f, 0.f, 0.f, 0.f, 0.f};
    for (int ic = 0; ic < 64; ic++) {
#pragma unroll
        for (int kr = 0; kr < 3; kr++) {
            const float* inrow = in_s + (ic * 3 + kr) * 34 + px;
            const float* wrow  = w_s + (ic * 9 + kr * 3) * 36 + co * 8;
#pragma unroll
            for (int kc = 0; kc < 3; kc++) {
                float val = inrow[kc];
                float4 wa = *(const float4*)(wrow + kc * 36);
                float4 wb = *(const float4*)(wrow + kc * 36 + 4);
                acc[0] += val * wa.x; acc[1] += val * wa.y;
                acc[2] += val * wa.z; acc[3] += val * wa.w;
                acc[4] += val * wb.x; acc[5] += val * wb.y;
                acc[6] += val * wb.z; acc[7] += val * wb.w;
            }
        }
    }
    int node  = b * 1024 + h * 32 + px;
    int cbase = cg * 32 + co * 8;
    float out[8];
#pragma unroll
    for (int j = 0; j < 8; j++) {
        int c = cbase + j;
        float sc = g[c] * rsqrtf(v[c] + BN_EPS);
        float sh = bb[c] - m[c] * sc;
        float y = (acc[j] + cb[c]) * sc + sh;
        out[j] = y > 0.f ? y : 0.f;
    }
    float* op = g_nodes0 + node * 128 + cbase;
    *(float4*)op       = make_float4(out[0], out[1], out[2], out[3]);
    *(float4*)(op + 4) = make_float4(out[4], out[5], out[6], out[7]);
}

// ---------------- plain 64x64 tiled SGEMM (row-major A[MxK] * B[KxN]) ----------------
__global__ __launch_bounds__(256) void sgemm_kernel(
    const float* __restrict__ A, const float* __restrict__ B,
    float* __restrict__ C, int M, int N, int K)
{
    __shared__ float As[16][68];
    __shared__ float Bs[16][64];
    int t = threadIdx.x;
    int bm = blockIdx.y * 64, bn = blockIdx.x * 64;
    int tx = t & 15, ty = t >> 4;
    int arow = t >> 2, ak = (t & 3) * 4;
    int bk = t >> 4, bn4 = (t & 15) * 4;
    float acc[4][4] = {};
    for (int k0 = 0; k0 < K; k0 += 16) {
        float4 a = *(const float4*)&A[(bm + arow) * K + k0 + ak];
        As[ak + 0][arow] = a.x; As[ak + 1][arow] = a.y;
        As[ak + 2][arow] = a.z; As[ak + 3][arow] = a.w;
        float4 bvl = *(const float4*)&B[(k0 + bk) * N + bn + bn4];
        *(float4*)&Bs[bk][bn4] = bvl;
        __syncthreads();
#pragma unroll
        for (int k = 0; k < 16; k++) {
            float4 av = *(const float4*)&As[k][ty * 4];
            float4 bv = *(const float4*)&Bs[k][tx * 4];
            acc[0][0] += av.x * bv.x; acc[0][1] += av.x * bv.y; acc[0][2] += av.x * bv.z; acc[0][3] += av.x * bv.w;
            acc[1][0] += av.y * bv.x; acc[1][1] += av.y * bv.y; acc[1][2] += av.y * bv.z; acc[1][3] += av.y * bv.w;
            acc[2][0] += av.z * bv.x; acc[2][1] += av.z * bv.y; acc[2][2] += av.z * bv.z; acc[2][3] += av.z * bv.w;
            acc[3][0] += av.w * bv.x; acc[3][1] += av.w * bv.y; acc[3][2] += av.w * bv.z; acc[3][3] += av.w * bv.w;
        }
        __syncthreads();
    }
#pragma unroll
    for (int i = 0; i < 4; i++) {
        int row = bm + ty * 4 + i;
        *(float4*)&C[row * N + bn + tx * 4] =
            make_float4(acc[i][0], acc[i][1], acc[i][2], acc[i][3]);
    }
}

// ---------------- per-node attention scores s=h@a_src, d=h@a_dst (first 1024 nodes) ----------------
__global__ __launch_bounds__(256) void sd_kernel(
    const float* __restrict__ h, const float* __restrict__ asrc,
    const float* __restrict__ adst, int D)
{
    int node = blockIdx.x * 8 + (threadIdx.x >> 5);
    int lane = threadIdx.x & 31;
    const float* hp = h + node * D;
    float ss = 0.f, dd = 0.f;
    for (int f = lane; f < D; f += 32) {
        float val = hp[f];
        ss += val * asrc[f];
        dd += val * adst[f];
    }
#pragma unroll
    for (int o = 16; o > 0; o >>= 1) {
        ss += __shfl_xor_sync(0xffffffffu, ss, o);
        dd += __shfl_xor_sync(0xffffffffu, dd, o);
    }
    if (lane == 0) { g_s[node] = ss; g_d[node] = dd; }
}

// ---------------- dense attention over first 1024 nodes, 8 dests per block ----------------
// out[j] = relu( (sum_i softmax_i(leaky(s_i+d_j)) * h_i) + bias ),  j in [blk*8, blk*8+8)
template <int D, int BS>
__global__ __launch_bounds__(BS) void attn_kernel(
    const float* __restrict__ h, const float* __restrict__ bias,
    float* __restrict__ out)
{
    __shared__ float w_s[1024 * 8];
    __shared__ float red[BS * 8];
    __shared__ float mx_s[8], inv_s[8], dv_s[8];
    int t = threadIdx.x;
    int j0 = blockIdx.x * 8;
    if (t < 8) dv_s[t] = g_d[j0 + t];
    __syncthreads();

    const int IT = 1024 / BS;
    float lmax[8];
#pragma unroll
    for (int j = 0; j < 8; j++) lmax[j] = -1e30f;
#pragma unroll
    for (int it = 0; it < IT; it++) {
        int i = t + it * BS;
        float si = g_s[i];
#pragma unroll
        for (int j = 0; j < 8; j++) {
            float e = si + dv_s[j];
            e = e > 0.f ? e : 0.2f * e;
            w_s[i * 8 + j] = e;
            lmax[j] = fmaxf(lmax[j], e);
        }
    }
#pragma unroll
    for (int j = 0; j < 8; j++) red[t * 8 + j] = lmax[j];
    __syncthreads();
    {
        int lane = t & 31;
        for (int wj = t >> 5; wj < 8; wj += BS / 32) {
            float mval = -1e30f;
            for (int r = lane; r < BS; r += 32) mval = fmaxf(mval, red[r * 8 + wj]);
#pragma unroll
            for (int o = 16; o > 0; o >>= 1)
                mval = fmaxf(mval, __shfl_xor_sync(0xffffffffu, mval, o));
            if (lane == 0) mx_s[wj] = mval;
        }
    }
    __syncthreads();

    float lsum[8] = {0.f, 0.f, 0.f, 0.f, 0.f, 0.f, 0.f, 0.f};
#pragma unroll
    for (int it = 0; it < IT; it++) {
        int i = t + it * BS;
#pragma unroll
        for (int j = 0; j < 8; j++) {
            float wv = __expf(w_s[i * 8 + j] - mx_s[j]);
            w_s[i * 8 + j] = wv;
            lsum[j] += wv;
        }
    }
    __syncthreads();
#pragma unroll
    for (int j = 0; j < 8; j++) red[t * 8 + j] = lsum[j];
    __syncthreads();
    {
        int lane = t & 31;
        for (int wj = t >> 5; wj < 8; wj += BS / 32) {
            float sval = 0.f;
            for (int r = lane; r < BS; r += 32) sval += red[r * 8 + wj];
#pragma unroll
            for (int o = 16; o > 0; o >>= 1)
                sval += __shfl_xor_sync(0xffffffffu, sval, o);
            if (lane == 0) inv_s[wj] = 1.0f / sval;
        }
    }
    __syncthreads();

    // phase 2: thread = feature (BS == D), 8 dest accumulators
    float acc[8] = {0.f, 0.f, 0.f, 0.f, 0.f, 0.f, 0.f, 0.f};
    const float* hp = h + t;
#pragma unroll 4
    for (int i = 0; i < 1024; i++) {
        float val = hp[i * D];
        float4 wa = *(const float4*)&w_s[i * 8];
        float4 wb = *(const float4*)&w_s[i * 8 + 4];
        acc[0] += wa.x * val; acc[1] += wa.y * val;
        acc[2] += wa.z * val; acc[3] += wa.w * val;
        acc[4] += wb.x * val; acc[5] += wb.y * val;
        acc[6] += wb.z * val; acc[7] += wb.w * val;
    }
    float bf = bias[t];
#pragma unroll
    for (int j = 0; j < 8; j++) {
        float y = acc[j] * inv_s[j] + bf;
        out[(j0 + j) * D + t] = y > 0.f ? y : 0.f;
    }
}

// ---------------- nodes >= 1024: out = relu(h + bias) (self-loop only) ----------------
template <int D>
__global__ __launch_bounds__(256) void rest_kernel(
    const float* __restrict__ h, const float* __restrict__ bias,
    float* __restrict__ out)
{
    int idx = blockIdx.x * 256 + threadIdx.x;   // [0, 7168*D)
    int off = 1024 * D + idx;
    float y = h[off] + bias[idx & (D - 1)];
    out[off] = y > 0.f ? y : 0.f;
}

// ---------------- mean pool per image + linear(128->10) + log_softmax ----------------
__global__ __launch_bounds__(128) void final_kernel(
    const float* __restrict__ x, const float* __restrict__ W,
    const float* __restrict__ bo, float* __restrict__ out)
{
    __shared__ float meanv[128];
    __shared__ float logits[10];
    __shared__ float stats[2];
    int b = blockIdx.x;
    int t = threadIdx.x;
    const float* base = x + b * 1024 * 128;
    float acc = 0.f;
    for (int n = 0; n < 1024; n++) acc += base[n * 128 + t];
    meanv[t] = acc * (1.0f / 1024.0f);
    __syncthreads();
    if (t < 10) {
        float lg = bo[t];
        for (int f = 0; f < 128; f++) lg += meanv[f] * W[f * 10 + t];
        logits[t] = lg;
    }
    __syncthreads();
    if (t == 0) {
        float mv = -1e30f;
        for (int k = 0; k < 10; k++) mv = fmaxf(mv, logits[k]);
        float se = 0.f;
        for (int k = 0; k < 10; k++) se += expf(logits[k] - mv);
        stats[0] = mv;
        stats[1] = logf(se);
    }
    __syncthreads();
    if (t < 10) out[b * 10 + t] = logits[t] - stats[0] - stats[1];
}

// ---------------- launch ----------------
extern "C" void kernel_launch(void* const* d_in, const int* in_sizes, int n_in,
                              void* d_out, int out_size)
{
    const float* images  = (const float*)d_in[0];
    const float* conv1_w = (const float*)d_in[1];
    const float* conv1_b = (const float*)d_in[2];
    const float* bn1_g   = (const float*)d_in[3];
    const float* bn1_b   = (const float*)d_in[4];
    const float* bn1_m   = (const float*)d_in[5];
    const float* bn1_v   = (const float*)d_in[6];
    const float* conv2_w = (const float*)d_in[7];
    const float* conv2_b = (const float*)d_in[8];
    const float* bn2_g   = (const float*)d_in[9];
    const float* bn2_b   = (const float*)d_in[10];
    const float* bn2_m   = (const float*)d_in[11];
    const float* bn2_v   = (const float*)d_in[12];
    const float* gat1_w    = (const float*)d_in[13];
    const float* gat1_asrc = (const float*)d_in[14];
    const float* gat1_adst = (const float*)d_in[15];
    const float* gat1_bias = (const float*)d_in[16];
    const float* gat2_w    = (const float*)d_in[17];
    const float* gat2_asrc = (const float*)d_in[18];
    const float* gat2_adst = (const float*)d_in[19];
    const float* gat2_bias = (const float*)d_in[20];
    const float* out_w = (const float*)d_in[21];
    const float* out_b = (const float*)d_in[22];
    float* out = (float*)d_out;

    // conv1 + bn + relu + pool
    conv1_pool_kernel<<<2048, 256>>>(images, conv1_w, conv1_b, bn1_g, bn1_b, bn1_m, bn1_v);

    // conv2 + bn + relu -> node features
    const int CONV2_SMEM = (6528 + 20736) * 4;   // 109056 bytes
    cudaFuncSetAttribute(conv2_kernel, cudaFuncAttributeMaxDynamicSharedMemorySize, CONV2_SMEM);
    conv2_kernel<<<dim3(4, 32, 8), 128, CONV2_SMEM>>>(conv2_w, conv2_b, bn2_g, bn2_b, bn2_m, bn2_v);

    // GAT layer 1
    float* nodes0 = nullptr; cudaGetSymbolAddress((void**)&nodes0, g_nodes0);
    float* h1 = nullptr;     cudaGetSymbolAddress((void**)&h1, g_h1);
    float* x1 = nullptr;     cudaGetSymbolAddress((void**)&x1, g_x1);
    float* h2 = nullptr;     cudaGetSymbolAddress((void**)&h2, g_h2);
    float* x2 = nullptr;     cudaGetSymbolAddress((void**)&x2, g_x2);

    sgemm_kernel<<<dim3(256 / 64, 8192 / 64), 256>>>(nodes0, gat1_w, h1, 8192, 256, 128);
    sd_kernel<<<128, 256>>>(h1, gat1_asrc, gat1_adst, 256);
    attn_kernel<256, 256><<<128, 256>>>(h1, gat1_bias, x1);
    rest_kernel<256><<<7168 * 256 / 256, 256>>>(h1, gat1_bias, x1);

    // GAT layer 2
    sgemm_kernel<<<dim3(128 / 64, 8192 / 64), 256>>>(x1, gat2_w, h2, 8192, 128, 256);
    sd_kernel<<<128, 256>>>(h2, gat2_asrc, gat2_adst, 128);
    attn_kernel<128, 128><<<128, 128>>>(h2, gat2_bias, x2);
    rest_kernel<128><<<7168 * 128 / 256, 256>>>(h2, gat2_bias, x2);

    // pool + classifier + log_softmax
    final_kernel<<<8, 128>>>(x2, out_w, out_b, out);
}

// round 2
// speedup vs baseline: 1.2969x; 1.2969x over previous
#include <cuda_runtime.h>
#include <math.h>

typedef unsigned long long ull;
#define BN_EPS 1e-5f

// ---------------- scratch ----------------
__device__ float g_pool[8 * 64 * 32 * 32];     // pooled conv1 output
__device__ float g_w2t[576 * 128];             // transposed conv2 weights [rem][oc]
__device__ float g_nodes0[8192 * 128];         // node features after conv2
__device__ float g_h1[8192 * 256];
__device__ float g_x1[8192 * 256];
__device__ float g_h2[8192 * 128];
__device__ float g_x2[8192 * 128];
__device__ float g_s[1024];
__device__ float g_d[1024];
__device__ float g_part[64 * 128];

// ---------------- f32x2 helpers ----------------
__device__ __forceinline__ unsigned sptr(const void* p) {
    return (unsigned)__cvta_generic_to_shared(p);
}
__device__ __forceinline__ void lds2(ull& a, ull& b, unsigned addr) {
    asm volatile("ld.shared.v2.b64 {%0,%1},[%2];" : "=l"(a), "=l"(b) : "r"(addr));
}
__device__ __forceinline__ ull dupf(float v) {
    unsigned u = __float_as_uint(v);
    ull r;
    asm("mov.b64 %0,{%1,%1};" : "=l"(r) : "r"(u));
    return r;
}
__device__ __forceinline__ void ffma2(ull& d, ull a, ull b) {
    asm("fma.rn.f32x2 %0,%1,%2,%0;" : "+l"(d) : "l"(a), "l"(b));
}
union F2U { ull u; float2 f; };
__device__ __forceinline__ float2 upk(ull u) { F2U x; x.u = u; return x.f; }

// ---------------- conv1 + bias + BN + ReLU + 2x2 maxpool ----------------
__global__ __launch_bounds__(256) void conv1_pool_kernel(
    const float* __restrict__ img, const float* __restrict__ w,
    const float* __restrict__ cb, const float* __restrict__ g,
    const float* __restrict__ bb, const float* __restrict__ m,
    const float* __restrict__ v)
{
    __shared__ float ws[1728];
    __shared__ float sc_s[64], sh_s[64];
    int t = threadIdx.x;
    for (int i = t; i < 1728; i += 256) ws[i] = w[i];
    if (t < 64) {
        float sc = g[t] * rsqrtf(v[t] + BN_EPS);
        sc_s[t] = sc;
        sh_s[t] = bb[t] - m[t] * sc + cb[t] * sc;
    }
    __syncthreads();

    int idx = blockIdx.x * 256 + t;
    int pw = idx & 31;
    int ph = (idx >> 5) & 31;
    int c  = (idx >> 10) & 63;
    int b  = idx >> 16;

    float win[3][4][4];
    int h0 = 2 * ph - 1, w0 = 2 * pw - 1;
#pragma unroll
    for (int ic = 0; ic < 3; ic++) {
        const float* ip = img + (b * 3 + ic) * 4096;
#pragma unroll
        for (int r = 0; r < 4; r++) {
            int ih = h0 + r;
            bool rok = (unsigned)ih < 64u;
#pragma unroll
            for (int cc = 0; cc < 4; cc++) {
                int iw = w0 + cc;
                win[ic][r][cc] = (rok && (unsigned)iw < 64u) ? ip[ih * 64 + iw] : 0.0f;
            }
        }
    }
    const float* wc = ws + c * 27;
    float sc = sc_s[c], sh = sh_s[c];
    float mx = 0.0f;
#pragma unroll
    for (int dh = 0; dh < 2; dh++)
#pragma unroll
    for (int dw = 0; dw < 2; dw++) {
        float s = 0.f;
#pragma unroll
        for (int ic = 0; ic < 3; ic++)
#pragma unroll
        for (int kh = 0; kh < 3; kh++)
#pragma unroll
        for (int kw = 0; kw < 3; kw++)
            s += win[ic][dh + kh][dw + kw] * wc[ic * 9 + kh * 3 + kw];
        float y = s * sc + sh;
        y = y > 0.f ? y : 0.f;
        mx = fmaxf(mx, y);
    }
    g_pool[idx] = mx;
}

// ---------------- transpose conv2 weights [128oc][576] -> [576][128oc] ----------------
__global__ __launch_bounds__(256) void transpose_w2(const float* __restrict__ w2)
{
    int i = blockIdx.x * 256 + threadIdx.x;   // 73728 total
    int rem = i >> 7;
    int oc  = i & 127;
    g_w2t[i] = w2[oc * 576 + rem];
}

// ---------------- conv2 + bias + BN + ReLU -> node-major [8192,128], f32x2 ----------------
// grid (16 row-pairs, 8 images), 256 threads: px = t&31, cq = t>>5 (16 out channels each)
__global__ __launch_bounds__(256) void conv2_kernel(
    const float* __restrict__ cb, const float* __restrict__ g,
    const float* __restrict__ bb, const float* __restrict__ m,
    const float* __restrict__ v)
{
    __shared__ float in_s[1088];   // 8ic x 4rows x 34cols
    __shared__ float w_s[9216];    // 72 x 128 (rem-major, oc contiguous)
    int t  = threadIdx.x;
    int h0 = blockIdx.x * 2;
    int b  = blockIdx.y;
    int px = t & 31;
    int cq = t >> 5;
    unsigned wsa = sptr(w_s);

    ull acc[2][8];
#pragma unroll
    for (int r = 0; r < 2; r++)
#pragma unroll
    for (int j = 0; j < 8; j++) acc[r][j] = 0ull;

    for (int ic0 = 0; ic0 < 64; ic0 += 8) {
        __syncthreads();
        const float4* src = (const float4*)(g_w2t + ic0 * 9 * 128);
#pragma unroll
        for (int i = 0; i < 9; i++) ((float4*)w_s)[t + i * 256] = src[t + i * 256];
        for (int i = t; i < 1088; i += 256) {
            int ic  = i / 136;
            int rem = i - ic * 136;
            int r   = rem / 34;
            int col = rem - r * 34;
            int ri = h0 - 1 + r;
            int ci = col - 1;
            float val = 0.f;
            if ((unsigned)ri < 32u && (unsigned)ci < 32u)
                val = g_pool[((b * 64 + ic0 + ic) * 32 + ri) * 32 + ci];
            in_s[i] = val;
        }
        __syncthreads();
#pragma unroll 2
        for (int ic8 = 0; ic8 < 8; ic8++) {
#pragma unroll
            for (int kr = 0; kr < 3; kr++) {
                const float* prow = in_s + (ic8 * 4 + kr) * 34 + px;
#pragma unroll
                for (int kc = 0; kc < 3; kc++) {
                    unsigned wa = wsa + (((ic8 * 9 + kr * 3 + kc) << 7) + (cq << 4)) * 4u;
                    ull w0, w1, w2x, w3, w4, w5, w6, w7;
                    lds2(w0, w1, wa);
                    lds2(w2x, w3, wa + 16);
                    lds2(w4, w5, wa + 32);
                    lds2(w6, w7, wa + 48);
                    ull v0 = dupf(prow[kc]);
                    ull v1 = dupf(prow[kc + 34]);
                    ffma2(acc[0][0], v0, w0);  ffma2(acc[0][1], v0, w1);
                    ffma2(acc[0][2], v0, w2x); ffma2(acc[0][3], v0, w3);
                    ffma2(acc[0][4], v0, w4);  ffma2(acc[0][5], v0, w5);
                    ffma2(acc[0][6], v0, w6);  ffma2(acc[0][7], v0, w7);
                    ffma2(acc[1][0], v1, w0);  ffma2(acc[1][1], v1, w1);
                    ffma2(acc[1][2], v1, w2x); ffma2(acc[1][3], v1, w3);
                    ffma2(acc[1][4], v1, w4);  ffma2(acc[1][5], v1, w5);
                    ffma2(acc[1][6], v1, w6);  ffma2(acc[1][7], v1, w7);
                }
            }
        }
    }

    // BN scale/shift per channel (hoisted)
    float scs[16], shs[16];
#pragma unroll
    for (int j = 0; j < 16; j++) {
        int c = cq * 16 + j;
        float sc = g[c] * rsqrtf(v[c] + BN_EPS);
        scs[j] = sc;
        shs[j] = bb[c] - m[c] * sc + cb[c] * sc;
    }
#pragma unroll
    for (int r = 0; r < 2; r++) {
        int node = b * 1024 + (h0 + r) * 32 + px;
        float* op = g_nodes0 + node * 128 + cq * 16;
        float outv[16];
#pragma unroll
        for (int jp = 0; jp < 8; jp++) {
            float2 p = upk(acc[r][jp]);
            outv[2 * jp]     = p.x;
            outv[2 * jp + 1] = p.y;
        }
#pragma unroll
        for (int j = 0; j < 16; j++) {
            float y = outv[j] * scs[j] + shs[j];
            outv[j] = y > 0.f ? y : 0.f;
        }
#pragma unroll
        for (int q = 0; q < 4; q++)
            *(float4*)(op + q * 4) = *(float4*)&outv[q * 4];
    }
}

// ---------------- SGEMM (f32x2) + fused epilogue ----------------
// C[MxN] = A[MxK] @ B[KxN]; rows < 1024 -> raw H; rows >= 1024 -> X = relu(C + bias)
__global__ __launch_bounds__(256) void sgemm_fused(
    const float* __restrict__ A, const float* __restrict__ B,
    const float* __restrict__ bias, float* __restrict__ H,
    float* __restrict__ X, int M, int N, int K)
{
    __shared__ float As[16][128];   // duplicated rows: As[k][2r] = As[k][2r+1] = A[r][k]
    __shared__ float Bs[16][64];
    int t = threadIdx.x;
    int bm = blockIdx.y * 64, bn = blockIdx.x * 64;
    int tx = t & 15, ty = t >> 4;
    int arow = t >> 2, ak = (t & 3) * 4;
    int bk = t >> 4, bn4 = (t & 15) * 4;
    unsigned asA = sptr(&As[0][0]);
    unsigned asB = sptr(&Bs[0][0]);

    ull acc[4][2];
#pragma unroll
    for (int i = 0; i < 4; i++) { acc[i][0] = 0ull; acc[i][1] = 0ull; }

    for (int k0 = 0; k0 < K; k0 += 16) {
        float4 a = *(const float4*)&A[(bm + arow) * K + k0 + ak];
        *(float2*)&As[ak + 0][2 * arow] = make_float2(a.x, a.x);
        *(float2*)&As[ak + 1][2 * arow] = make_float2(a.y, a.y);
        *(float2*)&As[ak + 2][2 * arow] = make_float2(a.z, a.z);
        *(float2*)&As[ak + 3][2 * arow] = make_float2(a.w, a.w);
        *(float4*)&Bs[bk][bn4] = *(const float4*)&B[(k0 + bk) * N + bn + bn4];
        __syncthreads();
#pragma unroll
        for (int k = 0; k < 16; k++) {
            ull a01, a23, a45, a67, b01, b23;
            lds2(a01, a23, asA + (unsigned)(k * 512 + ty * 32));
            lds2(a45, a67, asA + (unsigned)(k * 512 + ty * 32 + 16));
            lds2(b01, b23, asB + (unsigned)(k * 256 + tx * 16));
            ffma2(acc[0][0], a01, b01); ffma2(acc[0][1], a01, b23);
            ffma2(acc[1][0], a23, b01); ffma2(acc[1][1], a23, b23);
            ffma2(acc[2][0], a45, b01); ffma2(acc[2][1], a45, b23);
            ffma2(acc[3][0], a67, b01); ffma2(acc[3][1], a67, b23);
        }
        __syncthreads();
    }

    if (bm < 1024) {
#pragma unroll
        for (int i = 0; i < 4; i++) {
            float2 lo = upk(acc[i][0]);
            float2 hi = upk(acc[i][1]);
            *(float4*)&H[(bm + ty * 4 + i) * N + bn + tx * 4] =
                make_float4(lo.x, lo.y, hi.x, hi.y);
        }
    } else {
        float4 bv = *(const float4*)&bias[bn + tx * 4];
#pragma unroll
        for (int i = 0; i < 4; i++) {
            float2 lo = upk(acc[i][0]);
            float2 hi = upk(acc[i][1]);
            float y0 = lo.x + bv.x; y0 = y0 > 0.f ? y0 : 0.f;
            float y1 = lo.y + bv.y; y1 = y1 > 0.f ? y1 : 0.f;
            float y2 = hi.x + bv.z; y2 = y2 > 0.f ? y2 : 0.f;
            float y3 = hi.y + bv.w; y3 = y3 > 0.f ? y3 : 0.f;
            *(float4*)&X[(bm + ty * 4 + i) * N + bn + tx * 4] =
                make_float4(y0, y1, y2, y3);
        }
    }
}

// ---------------- per-node attention scores (first 1024 nodes) ----------------
__global__ __launch_bounds__(256) void sd_kernel(
    const float* __restrict__ h, const float* __restrict__ asrc,
    const float* __restrict__ adst, int D)
{
    int node = blockIdx.x * 8 + (threadIdx.x >> 5);
    int lane = threadIdx.x & 31;
    const float4* hp = (const float4*)(h + node * D);
    const float4* as4 = (const float4*)asrc;
    const float4* ad4 = (const float4*)adst;
    float ss = 0.f, dd = 0.f;
    for (int f = lane; f < D / 4; f += 32) {
        float4 hv = hp[f], av = as4[f], dv = ad4[f];
        ss += hv.x * av.x + hv.y * av.y + hv.z * av.z + hv.w * av.w;
        dd += hv.x * dv.x + hv.y * dv.y + hv.z * dv.z + hv.w * dv.w;
    }
#pragma unroll
    for (int o = 16; o > 0; o >>= 1) {
        ss += __shfl_xor_sync(0xffffffffu, ss, o);
        dd += __shfl_xor_sync(0xffffffffu, dd, o);
    }
    if (lane == 0) { g_s[node] = ss; g_d[node] = dd; }
}

// ---------------- dense attention over first 1024 nodes, 8 dests/block, f32x2 ----------------
template <int D, int BS>
__global__ __launch_bounds__(BS) void attn_kernel(
    const float* __restrict__ h, const float* __restrict__ bias,
    float* __restrict__ out)
{
    __shared__ float w_s[1024 * 8];
    __shared__ float red[BS * 8];
    __shared__ float mx_s[8], inv_s[8], dv_s[8];
    int t = threadIdx.x;
    int j0 = blockIdx.x * 8;
    if (t < 8) dv_s[t] = g_d[j0 + t];
    __syncthreads();

    const int IT = 1024 / BS;
    float lmax[8];
#pragma unroll
    for (int j = 0; j < 8; j++) lmax[j] = -1e30f;
#pragma unroll
    for (int it = 0; it < IT; it++) {
        int i = t + it * BS;
        float si = g_s[i];
#pragma unroll
        for (int j = 0; j < 8; j++) {
            float e = si + dv_s[j];
            e = e > 0.f ? e : 0.2f * e;
            w_s[i * 8 + j] = e;
            lmax[j] = fmaxf(lmax[j], e);
        }
    }
#pragma unroll
    for (int j = 0; j < 8; j++) red[t * 8 + j] = lmax[j];
    __syncthreads();
    {
        int lane = t & 31;
        for (int wj = t >> 5; wj < 8; wj += BS / 32) {
            float mval = -1e30f;
            for (int r = lane; r < BS; r += 32) mval = fmaxf(mval, red[r * 8 + wj]);
#pragma unroll
            for (int o = 16; o > 0; o >>= 1)
                mval = fmaxf(mval, __shfl_xor_sync(0xffffffffu, mval, o));
            if (lane == 0) mx_s[wj] = mval;
        }
    }
    __syncthreads();

    float lsum[8] = {0.f, 0.f, 0.f, 0.f, 0.f, 0.f, 0.f, 0.f};
#pragma unroll
    for (int it = 0; it < IT; it++) {
        int i = t + it * BS;
#pragma unroll
        for (int j = 0; j < 8; j++) {
            float wv = __expf(w_s[i * 8 + j] - mx_s[j]);
            w_s[i * 8 + j] = wv;
            lsum[j] += wv;
        }
    }
    __syncthreads();
#pragma unroll
    for (int j = 0; j < 8; j++) red[t * 8 + j] = lsum[j];
    __syncthreads();
    {
        int lane = t & 31;
        for (int wj = t >> 5; wj < 8; wj += BS / 32) {
            float sval = 0.f;
            for (int r = lane; r < BS; r += 32) sval += red[r * 8 + wj];
#pragma unroll
            for (int o = 16; o > 0; o >>= 1)
                sval += __shfl_xor_sync(0xffffffffu, sval, o);
            if (lane == 0) inv_s[wj] = 1.0f / sval;
        }
    }
    __syncthreads();

    // phase 2: thread = feature, 8 dest accumulators (4 f32x2 pairs)
    unsigned wsa = sptr(w_s);
    ull acc2[4] = {0ull, 0ull, 0ull, 0ull};
    const float* hp = h + t;
#pragma unroll 4
    for (int i = 0; i < 1024; i++) {
        ull vd = dupf(hp[i * D]);
        ull w01, w23, w45, w67;
        lds2(w01, w23, wsa + (unsigned)(i * 32));
        lds2(w45, w67, wsa + (unsigned)(i * 32 + 16));
        ffma2(acc2[0], vd, w01);
        ffma2(acc2[1], vd, w23);
        ffma2(acc2[2], vd, w45);
        ffma2(acc2[3], vd, w67);
    }
    float bf = bias[t];
#pragma unroll
    for (int jp = 0; jp < 4; jp++) {
        float2 p = upk(acc2[jp]);
        float y0 = p.x * inv_s[2 * jp] + bf;
        float y1 = p.y * inv_s[2 * jp + 1] + bf;
        out[(j0 + 2 * jp) * D + t]     = y0 > 0.f ? y0 : 0.f;
        out[(j0 + 2 * jp + 1) * D + t] = y1 > 0.f ? y1 : 0.f;
    }
}

// ---------------- mean pool stage 1: partial sums over 128-node chunks ----------------
__global__ __launch_bounds__(128) void pool_partial_kernel()
{
    int b = blockIdx.x >> 3, ch = blockIdx.x & 7, t = threadIdx.x;
    const float* base = g_x2 + (b * 1024 + ch * 128) * 128;
    float acc = 0.f;
    for (int n = 0; n < 128; n++) acc += base[n * 128 + t];
    g_part[blockIdx.x * 128 + t] = acc;
}

// ---------------- stage 2: combine + linear(128->10) + log_softmax ----------------
__global__ __launch_bounds__(128) void final_kernel(
    const float* __restrict__ W, const float* __restrict__ bo,
    float* __restrict__ out)
{
    __shared__ float meanv[128];
    __shared__ float logits[10];
    __shared__ float stats[2];
    int b = blockIdx.x;
    int t = threadIdx.x;
    float acc = 0.f;
#pragma unroll
    for (int k = 0; k < 8; k++) acc += g_part[(b * 8 + k) * 128 + t];
    meanv[t] = acc * (1.0f / 1024.0f);
    __syncthreads();
    if (t < 10) {
        float lg = bo[t];
        for (int f = 0; f < 128; f++) lg += meanv[f] * W[f * 10 + t];
        logits[t] = lg;
    }
    __syncthreads();
    if (t == 0) {
        float mv = -1e30f;
        for (int k = 0; k < 10; k++) mv = fmaxf(mv, logits[k]);
        float se = 0.f;
        for (int k = 0; k < 10; k++) se += expf(logits[k] - mv);
        stats[0] = mv;
        stats[1] = logf(se);
    }
    __syncthreads();
    if (t < 10) out[b * 10 + t] = logits[t] - stats[0] - stats[1];
}

// ---------------- launch ----------------
extern "C" void kernel_launch(void* const* d_in, const int* in_sizes, int n_in,
                              void* d_out, int out_size)
{
    const float* images  = (const float*)d_in[0];
    const float* conv1_w = (const float*)d_in[1];
    const float* conv1_b = (const float*)d_in[2];
    const float* bn1_g   = (const float*)d_in[3];
    const float* bn1_b   = (const float*)d_in[4];
    const float* bn1_m   = (const float*)d_in[5];
    const float* bn1_v   = (const float*)d_in[6];
    const float* conv2_w = (const float*)d_in[7];
    const float* conv2_b = (const float*)d_in[8];
    const float* bn2_g   = (const float*)d_in[9];
    const float* bn2_b   = (const float*)d_in[10];
    const float* bn2_m   = (const float*)d_in[11];
    const float* bn2_v   = (const float*)d_in[12];
    const float* gat1_w    = (const float*)d_in[13];
    const float* gat1_asrc = (const float*)d_in[14];
    const float* gat1_adst = (const float*)d_in[15];
    const float* gat1_bias = (const float*)d_in[16];
    const float* gat2_w    = (const float*)d_in[17];
    const float* gat2_asrc = (const float*)d_in[18];
    const float* gat2_adst = (const float*)d_in[19];
    const float* gat2_bias = (const float*)d_in[20];
    const float* out_w = (const float*)d_in[21];
    const float* out_b = (const float*)d_in[22];
    float* out = (float*)d_out;

    float* nodes0 = nullptr; cudaGetSymbolAddress((void**)&nodes0, g_nodes0);
    float* h1 = nullptr;     cudaGetSymbolAddress((void**)&h1, g_h1);
    float* x1 = nullptr;     cudaGetSymbolAddress((void**)&x1, g_x1);
    float* h2 = nullptr;     cudaGetSymbolAddress((void**)&h2, g_h2);
    float* x2 = nullptr;     cudaGetSymbolAddress((void**)&x2, g_x2);

    conv1_pool_kernel<<<2048, 256>>>(images, conv1_w, conv1_b, bn1_g, bn1_b, bn1_m, bn1_v);
    transpose_w2<<<288, 256>>>(conv2_w);
    conv2_kernel<<<dim3(16, 8), 256>>>(conv2_b, bn2_g, bn2_b, bn2_m, bn2_v);

    // GAT layer 1 (rest-rows fused into sgemm epilogue)
    sgemm_fused<<<dim3(4, 128), 256>>>(nodes0, gat1_w, gat1_bias, h1, x1, 8192, 256, 128);
    sd_kernel<<<128, 256>>>(h1, gat1_asrc, gat1_adst, 256);
    attn_kernel<256, 256><<<128, 256>>>(h1, gat1_bias, x1);

    // GAT layer 2
    sgemm_fused<<<dim3(2, 128), 256>>>(x1, gat2_w, gat2_bias, h2, x2, 8192, 128, 256);
    sd_kernel<<<128, 256>>>(h2, gat2_asrc, gat2_adst, 128);
    attn_kernel<128, 128><<<128, 128>>>(h2, gat2_bias, x2);

    pool_partial_kernel<<<64, 128>>>();
    final_kernel<<<8, 128>>>(out_w, out_b, out);
}

// round 3
// speedup vs baseline: 2.1147x; 1.6306x over previous
#include <cuda_runtime.h>
#include <math.h>

typedef unsigned long long ull;
#define BN_EPS 1e-5f

// ---------------- scratch ----------------
__device__ float g_pool[8 * 64 * 32 * 32];
__device__ float g_w2t[576 * 128];
__device__ float g_nodes0[8192 * 128];
__device__ float g_h1[8192 * 256];
__device__ float g_x1[8192 * 256];
__device__ float g_h2[8192 * 128];
__device__ float g_x2[8192 * 128];
__device__ float g_s1p[1024 * 4];
__device__ float g_d1p[1024 * 4];
__device__ float g_s2p[1024 * 2];
__device__ float g_d2p[1024 * 2];
__device__ float g_part[64 * 128];

// ---------------- f32x2 helpers ----------------
__device__ __forceinline__ unsigned sptr(const void* p) {
    return (unsigned)__cvta_generic_to_shared(p);
}
__device__ __forceinline__ void lds2(ull& a, ull& b, unsigned addr) {
    asm volatile("ld.shared.v2.b64 {%0,%1},[%2];" : "=l"(a), "=l"(b) : "r"(addr));
}
__device__ __forceinline__ ull dupf(float v) {
    unsigned u = __float_as_uint(v);
    ull r;
    asm("mov.b64 %0,{%1,%1};" : "=l"(r) : "r"(u));
    return r;
}
__device__ __forceinline__ void ffma2(ull& d, ull a, ull b) {
    asm("fma.rn.f32x2 %0,%1,%2,%0;" : "+l"(d) : "l"(a), "l"(b));
}
union F2U { ull u; float2 f; };
__device__ __forceinline__ float2 upk(ull u) { F2U x; x.u = u; return x.f; }

// ---------------- stage1: conv1+bn+relu+pool (blocks <2048) | w2 transpose (rest) ----------------
__global__ __launch_bounds__(256) void stage1_kernel(
    const float* __restrict__ img, const float* __restrict__ w,
    const float* __restrict__ cb, const float* __restrict__ g,
    const float* __restrict__ bb, const float* __restrict__ m,
    const float* __restrict__ v, const float* __restrict__ w2)
{
    __shared__ float ws[1728];
    __shared__ float sc_s[64], sh_s[64];
    int t = threadIdx.x;

    if (blockIdx.x >= 2048) {
        int i = (blockIdx.x - 2048) * 256 + t;      // 73728 total
        int rem = i >> 7, oc = i & 127;
        g_w2t[i] = w2[oc * 576 + rem];
        return;
    }

    for (int i = t; i < 1728; i += 256) ws[i] = w[i];
    if (t < 64) {
        float sc = g[t] * rsqrtf(v[t] + BN_EPS);
        sc_s[t] = sc;
        sh_s[t] = bb[t] - m[t] * sc + cb[t] * sc;
    }
    __syncthreads();

    int idx = blockIdx.x * 256 + t;
    int pw = idx & 31;
    int ph = (idx >> 5) & 31;
    int c  = (idx >> 10) & 63;
    int b  = idx >> 16;

    float win[3][4][4];
    int h0 = 2 * ph - 1, w0 = 2 * pw - 1;
#pragma unroll
    for (int ic = 0; ic < 3; ic++) {
        const float* ip = img + (b * 3 + ic) * 4096;
#pragma unroll
        for (int r = 0; r < 4; r++) {
            int ih = h0 + r;
            bool rok = (unsigned)ih < 64u;
#pragma unroll
            for (int cc = 0; cc < 4; cc++) {
                int iw = w0 + cc;
                win[ic][r][cc] = (rok && (unsigned)iw < 64u) ? ip[ih * 64 + iw] : 0.0f;
            }
        }
    }
    const float* wc = ws + c * 27;
    float sc = sc_s[c], sh = sh_s[c];
    float mx = 0.0f;
#pragma unroll
    for (int dh = 0; dh < 2; dh++)
#pragma unroll
    for (int dw = 0; dw < 2; dw++) {
        float s = 0.f;
#pragma unroll
        for (int ic = 0; ic < 3; ic++)
#pragma unroll
        for (int kh = 0; kh < 3; kh++)
#pragma unroll
        for (int kw = 0; kw < 3; kw++)
            s += win[ic][dh + kh][dw + kw] * wc[ic * 9 + kh * 3 + kw];
        float y = s * sc + sh;
        y = y > 0.f ? y : 0.f;
        mx = fmaxf(mx, y);
    }
    g_pool[idx] = mx;
}

// ---------------- conv2 + bias + BN + ReLU -> node-major [8192,128], f32x2 ----------------
__global__ __launch_bounds__(256) void conv2_kernel(
    const float* __restrict__ cb, const float* __restrict__ g,
    const float* __restrict__ bb, const float* __restrict__ m,
    const float* __restrict__ v)
{
    __shared__ float in_s[1088];   // 8ic x 4rows x 34cols
    __shared__ float w_s[9216];    // 72 x 128
    int t  = threadIdx.x;
    int h0 = blockIdx.x * 2;
    int b  = blockIdx.y;
    int px = t & 31;
    int cq = t >> 5;
    unsigned wsa = sptr(w_s);

    ull acc[2][8];
#pragma unroll
    for (int r = 0; r < 2; r++)
#pragma unroll
    for (int j = 0; j < 8; j++) acc[r][j] = 0ull;

    for (int ic0 = 0; ic0 < 64; ic0 += 8) {
        __syncthreads();
        const float4* src = (const float4*)(g_w2t + ic0 * 9 * 128);
#pragma unroll
        for (int i = 0; i < 9; i++) ((float4*)w_s)[t + i * 256] = src[t + i * 256];
        for (int i = t; i < 1088; i += 256) {
            int ic  = i / 136;
            int rem = i - ic * 136;
            int r   = rem / 34;
            int col = rem - r * 34;
            int ri = h0 - 1 + r;
            int ci = col - 1;
            float val = 0.f;
            if ((unsigned)ri < 32u && (unsigned)ci < 32u)
                val = g_pool[((b * 64 + ic0 + ic) * 32 + ri) * 32 + ci];
            in_s[i] = val;
        }
        __syncthreads();
#pragma unroll 2
        for (int ic8 = 0; ic8 < 8; ic8++) {
#pragma unroll
            for (int kr = 0; kr < 3; kr++) {
                const float* prow = in_s + (ic8 * 4 + kr) * 34 + px;
#pragma unroll
                for (int kc = 0; kc < 3; kc++) {
                    unsigned wa = wsa + (((ic8 * 9 + kr * 3 + kc) << 7) + (cq << 4)) * 4u;
                    ull w0, w1, w2x, w3, w4, w5, w6, w7;
                    lds2(w0, w1, wa);
                    lds2(w2x, w3, wa + 16);
                    lds2(w4, w5, wa + 32);
                    lds2(w6, w7, wa + 48);
                    ull v0 = dupf(prow[kc]);
                    ull v1 = dupf(prow[kc + 34]);
                    ffma2(acc[0][0], v0, w0);  ffma2(acc[0][1], v0, w1);
                    ffma2(acc[0][2], v0, w2x); ffma2(acc[0][3], v0, w3);
                    ffma2(acc[0][4], v0, w4);  ffma2(acc[0][5], v0, w5);
                    ffma2(acc[0][6], v0, w6);  ffma2(acc[0][7], v0, w7);
                    ffma2(acc[1][0], v1, w0);  ffma2(acc[1][1], v1, w1);
                    ffma2(acc[1][2], v1, w2x); ffma2(acc[1][3], v1, w3);
                    ffma2(acc[1][4], v1, w4);  ffma2(acc[1][5], v1, w5);
                    ffma2(acc[1][6], v1, w6);  ffma2(acc[1][7], v1, w7);
                }
            }
        }
    }

    float scs[16], shs[16];
#pragma unroll
    for (int j = 0; j < 16; j++) {
        int c = cq * 16 + j;
        float sc = g[c] * rsqrtf(v[c] + BN_EPS);
        scs[j] = sc;
        shs[j] = bb[c] - m[c] * sc + cb[c] * sc;
    }
#pragma unroll
    for (int r = 0; r < 2; r++) {
        int node = b * 1024 + (h0 + r) * 32 + px;
        float* op = g_nodes0 + node * 128 + cq * 16;
        float outv[16];
#pragma unroll
        for (int jp = 0; jp < 8; jp++) {
            float2 p = upk(acc[r][jp]);
            outv[2 * jp]     = p.x;
            outv[2 * jp + 1] = p.y;
        }
#pragma unroll
        for (int j = 0; j < 16; j++) {
            float y = outv[j] * scs[j] + shs[j];
            outv[j] = y > 0.f ? y : 0.f;
        }
#pragma unroll
        for (int q = 0; q < 4; q++)
            *(float4*)(op + q * 4) = *(float4*)&outv[q * 4];
    }
}

// ---------------- SGEMM v3: 128x64 tile, 8x4/thread, double-buffered, fused epilogue ----------------
// rows <1024: store raw H + per-column-block s/d partials; rows >=1024: X = relu(C+bias)
__global__ __launch_bounds__(256) void sgemm_fused(
    const float* __restrict__ A, const float* __restrict__ B,
    const float* __restrict__ bias, const float* __restrict__ asrc,
    const float* __restrict__ adst, float* __restrict__ H,
    float* __restrict__ X, float* __restrict__ s_part,
    float* __restrict__ d_part, int N, int K)
{
    __shared__ float As[2][16][128];
    __shared__ float Bs[2][16][64];
    int t = threadIdx.x;
    int bm = blockIdx.y * 128, bn = blockIdx.x * 64;
    int tx = t & 15, ty = t >> 4;
    int ar = t >> 1, a8 = (t & 1) * 8;
    int bk = t >> 4, bc = (t & 15) * 4;
    const float* Aload = A + (size_t)(bm + ar) * K + a8;
    const float* Bload = B + (size_t)bk * N + bn + bc;
    unsigned bsB = sptr(Bs);

    float4 pa0 = *(const float4*)(Aload);
    float4 pa1 = *(const float4*)(Aload + 4);
    float4 pb  = *(const float4*)(Bload);

    ull acc[8][2];
#pragma unroll
    for (int i = 0; i < 8; i++) { acc[i][0] = 0ull; acc[i][1] = 0ull; }

    int NC = K >> 4;
    for (int ch = 0; ch < NC; ch++) {
        int p = ch & 1;
        As[p][a8 + 0][ar] = pa0.x; As[p][a8 + 1][ar] = pa0.y;
        As[p][a8 + 2][ar] = pa0.z; As[p][a8 + 3][ar] = pa0.w;
        As[p][a8 + 4][ar] = pa1.x; As[p][a8 + 5][ar] = pa1.y;
        As[p][a8 + 6][ar] = pa1.z; As[p][a8 + 7][ar] = pa1.w;
        *(float4*)&Bs[p][bk][bc] = pb;
        __syncthreads();
        if (ch + 1 < NC) {
            pa0 = *(const float4*)(Aload + (ch + 1) * 16);
            pa1 = *(const float4*)(Aload + (ch + 1) * 16 + 4);
            pb  = *(const float4*)(Bload + (size_t)(ch + 1) * 16 * N);
        }
        unsigned bbase = bsB + (unsigned)p * 4096u + (unsigned)tx * 16u;
#pragma unroll
        for (int k = 0; k < 16; k++) {
            float4 a0 = *(const float4*)&As[p][k][ty * 8];
            float4 a1 = *(const float4*)&As[p][k][ty * 8 + 4];
            ull b01, b23;
            lds2(b01, b23, bbase + (unsigned)k * 256u);
            ull d;
            d = dupf(a0.x); ffma2(acc[0][0], d, b01); ffma2(acc[0][1], d, b23);
            d = dupf(a0.y); ffma2(acc[1][0], d, b01); ffma2(acc[1][1], d, b23);
            d = dupf(a0.z); ffma2(acc[2][0], d, b01); ffma2(acc[2][1], d, b23);
            d = dupf(a0.w); ffma2(acc[3][0], d, b01); ffma2(acc[3][1], d, b23);
            d = dupf(a1.x); ffma2(acc[4][0], d, b01); ffma2(acc[4][1], d, b23);
            d = dupf(a1.y); ffma2(acc[5][0], d, b01); ffma2(acc[5][1], d, b23);
            d = dupf(a1.z); ffma2(acc[6][0], d, b01); ffma2(acc[6][1], d, b23);
            d = dupf(a1.w); ffma2(acc[7][0], d, b01); ffma2(acc[7][1], d, b23);
        }
    }

    float c[8][4];
#pragma unroll
    for (int rr = 0; rr < 8; rr++) {
        float2 lo = upk(acc[rr][0]);
        float2 hi = upk(acc[rr][1]);
        c[rr][0] = lo.x; c[rr][1] = lo.y; c[rr][2] = hi.x; c[rr][3] = hi.y;
    }
    int col = bn + tx * 4;

    if (bm >= 1024) {
        float4 bv = *(const float4*)&bias[col];
#pragma unroll
        for (int rr = 0; rr < 8; rr++) {
            float y0 = c[rr][0] + bv.x; y0 = y0 > 0.f ? y0 : 0.f;
            float y1 = c[rr][1] + bv.y; y1 = y1 > 0.f ? y1 : 0.f;
            float y2 = c[rr][2] + bv.z; y2 = y2 > 0.f ? y2 : 0.f;
            float y3 = c[rr][3] + bv.w; y3 = y3 > 0.f ? y3 : 0.f;
            *(float4*)&X[(size_t)(bm + ty * 8 + rr) * N + col] =
                make_float4(y0, y1, y2, y3);
        }
    } else {
        float4 av = *(const float4*)&asrc[col];
        float4 dv = *(const float4*)&adst[col];
        int NB = gridDim.x;
#pragma unroll
        for (int rr = 0; rr < 8; rr++) {
            *(float4*)&H[(size_t)(bm + ty * 8 + rr) * N + col] =
                make_float4(c[rr][0], c[rr][1], c[rr][2], c[rr][3]);
            float sp = c[rr][0] * av.x + c[rr][1] * av.y + c[rr][2] * av.z + c[rr][3] * av.w;
            float dp = c[rr][0] * dv.x + c[rr][1] * dv.y + c[rr][2] * dv.z + c[rr][3] * dv.w;
#pragma unroll
            for (int off = 8; off > 0; off >>= 1) {
                sp += __shfl_xor_sync(0xffffffffu, sp, off);
                dp += __shfl_xor_sync(0xffffffffu, dp, off);
            }
            if ((t & 15) == 0) {
                int row = bm + ty * 8 + rr;
                s_part[row * NB + blockIdx.x] = sp;
                d_part[row * NB + blockIdx.x] = dp;
            }
        }
    }
}

// ---------------- dense attention, 8 dests/block, 256 threads ----------------
template <int D, int IG, int NB>
__global__ __launch_bounds__(256) void attn_kernel(
    const float* __restrict__ h, const float* __restrict__ bias,
    float* __restrict__ out, const float* __restrict__ s_part,
    const float* __restrict__ d_part)
{
    __shared__ float w_s[8192];
    __shared__ float red[2048];
    __shared__ float mx_s[8], inv_s[8], dv_s[8];
    int t = threadIdx.x;
    int j0 = blockIdx.x * 8;
    if (t < 8) {
        float dd = 0.f;
#pragma unroll
        for (int nb = 0; nb < NB; nb++) dd += d_part[(j0 + t) * NB + nb];
        dv_s[t] = dd;
    }
    __syncthreads();

    // phase 1: scores + softmax stats
    float lmax[8];
#pragma unroll
    for (int j = 0; j < 8; j++) lmax[j] = -1e30f;
#pragma unroll
    for (int it = 0; it < 4; it++) {
        int i = t + it * 256;
        float si = 0.f;
#pragma unroll
        for (int nb = 0; nb < NB; nb++) si += s_part[i * NB + nb];
#pragma unroll
        for (int j = 0; j < 8; j++) {
            float e = si + dv_s[j];
            e = e > 0.f ? e : 0.2f * e;
            w_s[i * 8 + j] = e;
            lmax[j] = fmaxf(lmax[j], e);
        }
    }
#pragma unroll
    for (int j = 0; j < 8; j++) red[t * 8 + j] = lmax[j];
    __syncthreads();
    {
        int lane = t & 31;
        int wj = t >> 5;     // 8 warps, one j each
        float mval = -1e30f;
        for (int r = lane; r < 256; r += 32) mval = fmaxf(mval, red[r * 8 + wj]);
#pragma unroll
        for (int o = 16; o > 0; o >>= 1)
            mval = fmaxf(mval, __shfl_xor_sync(0xffffffffu, mval, o));
        if (lane == 0) mx_s[wj] = mval;
    }
    __syncthreads();

    float lsum[8] = {0.f, 0.f, 0.f, 0.f, 0.f, 0.f, 0.f, 0.f};
#pragma unroll
    for (int it = 0; it < 4; it++) {
        int i = t + it * 256;
#pragma unroll
        for (int j = 0; j < 8; j++) {
            float wv = __expf(w_s[i * 8 + j] - mx_s[j]);
            w_s[i * 8 + j] = wv;
            lsum[j] += wv;
        }
    }
    __syncthreads();
#pragma unroll
    for (int j = 0; j < 8; j++) red[t * 8 + j] = lsum[j];
    __syncthreads();
    {
        int lane = t & 31;
        int wj = t >> 5;
        float sval = 0.f;
        for (int r = lane; r < 256; r += 32) sval += red[r * 8 + wj];
#pragma unroll
        for (int o = 16; o > 0; o >>= 1)
            sval += __shfl_xor_sync(0xffffffffu, sval, o);
        if (lane == 0) inv_s[wj] = 1.0f / sval;
    }
    __syncthreads();

    // phase 2: thread = 4 features, i-range split across IG groups
    const int FG = D / 4;
    int fg = t % FG;
    int ig = t / FG;
    const int ITER = 1024 / IG;
    ull acc2[8][2];
#pragma unroll
    for (int j = 0; j < 8; j++) { acc2[j][0] = 0ull; acc2[j][1] = 0ull; }
    const float4* wsp = (const float4*)w_s;
    int i0 = ig * ITER;
#pragma unroll 4
    for (int ii = 0; ii < ITER; ii++) {
        int i = i0 + ii;
        ulonglong2 hv = *(const ulonglong2*)(h + (size_t)i * D + fg * 4);
        float4 w0 = wsp[i * 2];
        float4 w1 = wsp[i * 2 + 1];
        ull d;
        d = dupf(w0.x); ffma2(acc2[0][0], d, hv.x); ffma2(acc2[0][1], d, hv.y);
        d = dupf(w0.y); ffma2(acc2[1][0], d, hv.x); ffma2(acc2[1][1], d, hv.y);
        d = dupf(w0.z); ffma2(acc2[2][0], d, hv.x); ffma2(acc2[2][1], d, hv.y);
        d = dupf(w0.w); ffma2(acc2[3][0], d, hv.x); ffma2(acc2[3][1], d, hv.y);
        d = dupf(w1.x); ffma2(acc2[4][0], d, hv.x); ffma2(acc2[4][1], d, hv.y);
        d = dupf(w1.y); ffma2(acc2[5][0], d, hv.x); ffma2(acc2[5][1], d, hv.y);
        d = dupf(w1.z); ffma2(acc2[6][0], d, hv.x); ffma2(acc2[6][1], d, hv.y);
        d = dupf(w1.w); ffma2(acc2[7][0], d, hv.x); ffma2(acc2[7][1], d, hv.y);
    }
    __syncthreads();          // all reads of w_s weights done
#pragma unroll
    for (int j = 0; j < 8; j++) {
        float2 lo = upk(acc2[j][0]);
        float2 hi = upk(acc2[j][1]);
        *(float4*)&w_s[ig * 8 * D + j * D + fg * 4] =
            make_float4(lo.x, lo.y, hi.x, hi.y);
    }
    __syncthreads();

    const int OUT = 8 * D;
#pragma unroll
    for (int k = 0; k < OUT / 256; k++) {
        int o = t + k * 256;
        int j = o / D, f = o % D;
        float sum = 0.f;
#pragma unroll
        for (int g2 = 0; g2 < IG; g2++) sum += w_s[g2 * OUT + o];
        float y = sum * inv_s[j] + bias[f];
        out[(size_t)(j0 + j) * D + f] = y > 0.f ? y : 0.f;
    }
}

// ---------------- mean pool stage 1 ----------------
__global__ __launch_bounds__(128) void pool_partial_kernel()
{
    int b = blockIdx.x >> 3, ch = blockIdx.x & 7, t = threadIdx.x;
    const float* base = g_x2 + (b * 1024 + ch * 128) * 128;
    float acc = 0.f;
    for (int n = 0; n < 128; n++) acc += base[n * 128 + t];
    g_part[blockIdx.x * 128 + t] = acc;
}

// ---------------- stage 2: combine + linear + log_softmax ----------------
__global__ __launch_bounds__(128) void final_kernel(
    const float* __restrict__ W, const float* __restrict__ bo,
    float* __restrict__ out)
{
    __shared__ float meanv[128];
    __shared__ float logits[10];
    __shared__ float stats[2];
    int b = blockIdx.x;
    int t = threadIdx.x;
    float acc = 0.f;
#pragma unroll
    for (int k = 0; k < 8; k++) acc += g_part[(b * 8 + k) * 128 + t];
    meanv[t] = acc * (1.0f / 1024.0f);
    __syncthreads();
    if (t < 10) {
        float lg = bo[t];
        for (int f = 0; f < 128; f++) lg += meanv[f] * W[f * 10 + t];
        logits[t] = lg;
    }
    __syncthreads();
    if (t == 0) {
        float mv = -1e30f;
        for (int k = 0; k < 10; k++) mv = fmaxf(mv, logits[k]);
        float se = 0.f;
        for (int k = 0; k < 10; k++) se += expf(logits[k] - mv);
        stats[0] = mv;
        stats[1] = logf(se);
    }
    __syncthreads();
    if (t < 10) out[b * 10 + t] = logits[t] - stats[0] - stats[1];
}

// ---------------- launch ----------------
extern "C" void kernel_launch(void* const* d_in, const int* in_sizes, int n_in,
                              void* d_out, int out_size)
{
    const float* images  = (const float*)d_in[0];
    const float* conv1_w = (const float*)d_in[1];
    const float* conv1_b = (const float*)d_in[2];
    const float* bn1_g   = (const float*)d_in[3];
    const float* bn1_b   = (const float*)d_in[4];
    const float* bn1_m   = (const float*)d_in[5];
    const float* bn1_v   = (const float*)d_in[6];
    const float* conv2_w = (const float*)d_in[7];
    const float* conv2_b = (const float*)d_in[8];
    const float* bn2_g   = (const float*)d_in[9];
    const float* bn2_b   = (const float*)d_in[10];
    const float* bn2_m   = (const float*)d_in[11];
    const float* bn2_v   = (const float*)d_in[12];
    const float* gat1_w    = (const float*)d_in[13];
    const float* gat1_asrc = (const float*)d_in[14];
    const float* gat1_adst = (const float*)d_in[15];
    const float* gat1_bias = (const float*)d_in[16];
    const float* gat2_w    = (const float*)d_in[17];
    const float* gat2_asrc = (const float*)d_in[18];
    const float* gat2_adst = (const float*)d_in[19];
    const float* gat2_bias = (const float*)d_in[20];
    const float* out_w = (const float*)d_in[21];
    const float* out_b = (const float*)d_in[22];
    float* out = (float*)d_out;

    float* nodes0 = nullptr; cudaGetSymbolAddress((void**)&nodes0, g_nodes0);
    float* h1 = nullptr;     cudaGetSymbolAddress((void**)&h1, g_h1);
    float* x1 = nullptr;     cudaGetSymbolAddress((void**)&x1, g_x1);
    float* h2 = nullptr;     cudaGetSymbolAddress((void**)&h2, g_h2);
    float* x2 = nullptr;     cudaGetSymbolAddress((void**)&x2, g_x2);
    float* s1p = nullptr;    cudaGetSymbolAddress((void**)&s1p, g_s1p);
    float* d1p = nullptr;    cudaGetSymbolAddress((void**)&d1p, g_d1p);
    float* s2p = nullptr;    cudaGetSymbolAddress((void**)&s2p, g_s2p);
    float* d2p = nullptr;    cudaGetSymbolAddress((void**)&d2p, g_d2p);

    stage1_kernel<<<2048 + 288, 256>>>(images, conv1_w, conv1_b, bn1_g, bn1_b,
                                       bn1_m, bn1_v, conv2_w);
    conv2_kernel<<<dim3(16, 8), 256>>>(conv2_b, bn2_g, bn2_b, bn2_m, bn2_v);

    // GAT layer 1
    sgemm_fused<<<dim3(4, 64), 256>>>(nodes0, gat1_w, gat1_bias, gat1_asrc,
                                      gat1_adst, h1, x1, s1p, d1p, 256, 128);
    attn_kernel<256, 4, 4><<<128, 256>>>(h1, gat1_bias, x1, s1p, d1p);

    // GAT layer 2
    sgemm_fused<<<dim3(2, 64), 256>>>(x1, gat2_w, gat2_bias, gat2_asrc,
                                      gat2_adst, h2, x2, s2p, d2p, 128, 256);
    attn_kernel<128, 8, 2><<<128, 256>>>(h2, gat2_bias, x2, s2p, d2p);

    pool_partial_kernel<<<64, 128>>>();
    final_kernel<<<8, 128>>>(out_w, out_b, out);
}

// round 5
// speedup vs baseline: 2.2384x; 1.0585x over previous
#include <cuda_runtime.h>
#include <math.h>

typedef unsigned long long ull;
#define BN_EPS 1e-5f

// ---------------- scratch ----------------
__device__ float g_pool[8 * 64 * 32 * 32];
__device__ float g_w2t[576 * 128];
__device__ float g_nodes0[8192 * 128];
__device__ float g_h1[8192 * 256];
__device__ float g_x1[8192 * 256];
__device__ float g_h2[8192 * 128];
__device__ float g_x2[8192 * 128];
__device__ float g_s1p[1024 * 4];
__device__ float g_d1p[1024 * 4];
__device__ float g_s2p[1024 * 2];
__device__ float g_d2p[1024 * 2];
__device__ float g_s[1024];
__device__ float g_d[1024];
__device__ float g_smaxp[4];
__device__ float g_psum[1024 * 4];
__device__ float g_apart[4 * 1024 * 256];
__device__ float g_part[64 * 128];

// ---------------- f32x2 helpers ----------------
__device__ __forceinline__ unsigned sptr(const void* p) {
    return (unsigned)__cvta_generic_to_shared(p);
}
__device__ __forceinline__ void lds2(ull& a, ull& b, unsigned addr) {
    asm volatile("ld.shared.v2.b64 {%0,%1},[%2];" : "=l"(a), "=l"(b) : "r"(addr));
}
__device__ __forceinline__ ull dupf(float v) {
    unsigned u = __float_as_uint(v);
    ull r;
    asm("mov.b64 %0,{%1,%1};" : "=l"(r) : "r"(u));
    return r;
}
__device__ __forceinline__ void ffma2(ull& d, ull a, ull b) {
    asm("fma.rn.f32x2 %0,%1,%2,%0;" : "+l"(d) : "l"(a), "l"(b));
}
union F2U { ull u; float2 f; };
__device__ __forceinline__ float2 upk(ull u) { F2U x; x.u = u; return x.f; }

// ---------------- stage1: conv1+bn+relu+pool | w2 transpose ----------------
__global__ __launch_bounds__(256) void stage1_kernel(
    const float* __restrict__ img, const float* __restrict__ w,
    const float* __restrict__ cb, const float* __restrict__ g,
    const float* __restrict__ bb, const float* __restrict__ m,
    const float* __restrict__ v, const float* __restrict__ w2)
{
    __shared__ float ws[1728];
    __shared__ float sc_s[64], sh_s[64];
    int t = threadIdx.x;

    if (blockIdx.x >= 2048) {
        int i = (blockIdx.x - 2048) * 256 + t;      // 73728 total
        int rem = i >> 7, oc = i & 127;
        g_w2t[i] = w2[oc * 576 + rem];
        return;
    }

    for (int i = t; i < 1728; i += 256) ws[i] = w[i];
    if (t < 64) {
        float sc = g[t] * rsqrtf(v[t] + BN_EPS);
        sc_s[t] = sc;
        sh_s[t] = bb[t] - m[t] * sc + cb[t] * sc;
    }
    __syncthreads();

    int idx = blockIdx.x * 256 + t;
    int pw = idx & 31;
    int ph = (idx >> 5) & 31;
    int c  = (idx >> 10) & 63;
    int b  = idx >> 16;

    float win[3][4][4];
    int h0 = 2 * ph - 1, w0 = 2 * pw - 1;
#pragma unroll
    for (int ic = 0; ic < 3; ic++) {
        const float* ip = img + (b * 3 + ic) * 4096;
#pragma unroll
        for (int r = 0; r < 4; r++) {
            int ih = h0 + r;
            bool rok = (unsigned)ih < 64u;
#pragma unroll
            for (int cc = 0; cc < 4; cc++) {
                int iw = w0 + cc;
                win[ic][r][cc] = (rok && (unsigned)iw < 64u) ? ip[ih * 64 + iw] : 0.0f;
            }
        }
    }
    const float* wc = ws + c * 27;
    float sc = sc_s[c], sh = sh_s[c];
    float mx = 0.0f;
#pragma unroll
    for (int dh = 0; dh < 2; dh++)
#pragma unroll
    for (int dw = 0; dw < 2; dw++) {
        float s = 0.f;
#pragma unroll
        for (int ic = 0; ic < 3; ic++)
#pragma unroll
        for (int kh = 0; kh < 3; kh++)
#pragma unroll
        for (int kw = 0; kw < 3; kw++)
            s += win[ic][dh + kh][dw + kw] * wc[ic * 9 + kh * 3 + kw];
        float y = s * sc + sh;
        y = y > 0.f ? y : 0.f;
        mx = fmaxf(mx, y);
    }
    g_pool[idx] = mx;
}

// ---------------- conv2: grid (16 row-pairs, 2 oc-halves, 8 imgs) ----------------
__global__ __launch_bounds__(256) void conv2_kernel(
    const float* __restrict__ cb, const float* __restrict__ g,
    const float* __restrict__ bb, const float* __restrict__ m,
    const float* __restrict__ v)
{
    __shared__ float in_s[1088];   // 8ic x 4rows x 34cols
    __shared__ float w_s[4608];    // 72 x 64 (rem-major, oc-half contiguous)
    int t  = threadIdx.x;
    int h0 = blockIdx.x * 2;
    int oh = blockIdx.y;
    int b  = blockIdx.z;
    int px = t & 31;
    int cq = t >> 5;
    unsigned wsa = sptr(w_s);

    ull acc[2][4];
#pragma unroll
    for (int r = 0; r < 2; r++)
#pragma unroll
    for (int j = 0; j < 4; j++) acc[r][j] = 0ull;

    const float4* w2t4 = (const float4*)g_w2t;
    for (int ic0 = 0; ic0 < 64; ic0 += 8) {
        __syncthreads();
        for (int i = t; i < 1152; i += 256) {
            int rem = i >> 4, q = i & 15;
            ((float4*)w_s)[i] = w2t4[(ic0 * 9 + rem) * 32 + oh * 16 + q];
        }
        for (int i = t; i < 1088; i += 256) {
            int ic  = i / 136;
            int rem = i - ic * 136;
            int r   = rem / 34;
            int col = rem - r * 34;
            int ri = h0 - 1 + r;
            int ci = col - 1;
            float val = 0.f;
            if ((unsigned)ri < 32u && (unsigned)ci < 32u)
                val = g_pool[((b * 64 + ic0 + ic) * 32 + ri) * 32 + ci];
            in_s[i] = val;
        }
        __syncthreads();
#pragma unroll 2
        for (int ic8 = 0; ic8 < 8; ic8++) {
#pragma unroll
            for (int kr = 0; kr < 3; kr++) {
                const float* prow = in_s + (ic8 * 4 + kr) * 34 + px;
#pragma unroll
                for (int kc = 0; kc < 3; kc++) {
                    unsigned wa = wsa + (((ic8 * 9 + kr * 3 + kc) << 6) + (cq << 3)) * 4u;
                    ull w0, w1, w2x, w3;
                    lds2(w0, w1, wa);
                    lds2(w2x, w3, wa + 16);
                    ull v0 = dupf(prow[kc]);
                    ull v1 = dupf(prow[kc + 34]);
                    ffma2(acc[0][0], v0, w0);  ffma2(acc[0][1], v0, w1);
                    ffma2(acc[0][2], v0, w2x); ffma2(acc[0][3], v0, w3);
                    ffma2(acc[1][0], v1, w0);  ffma2(acc[1][1], v1, w1);
                    ffma2(acc[1][2], v1, w2x); ffma2(acc[1][3], v1, w3);
                }
            }
        }
    }

    int cbase = oh * 64 + cq * 8;
    float scs[8], shs[8];
#pragma unroll
    for (int j = 0; j < 8; j++) {
        int c = cbase + j;
        float sc = g[c] * rsqrtf(v[c] + BN_EPS);
        scs[j] = sc;
        shs[j] = bb[c] - m[c] * sc + cb[c] * sc;
    }
#pragma unroll
    for (int r = 0; r < 2; r++) {
        int node = b * 1024 + (h0 + r) * 32 + px;
        float* op = g_nodes0 + node * 128 + cbase;
        float outv[8];
#pragma unroll
        for (int jp = 0; jp < 4; jp++) {
            float2 p = upk(acc[r][jp]);
            outv[2 * jp]     = p.x;
            outv[2 * jp + 1] = p.y;
        }
#pragma unroll
        for (int j = 0; j < 8; j++) {
            float y = outv[j] * scs[j] + shs[j];
            outv[j] = y > 0.f ? y : 0.f;
        }
        *(float4*)op       = *(float4*)&outv[0];
        *(float4*)(op + 4) = *(float4*)&outv[4];
    }
}

// ---------------- SGEMM: 128x64 tile, 8x4/thread, double-buffered, fused epilogue ----------------
__global__ __launch_bounds__(256) void sgemm_fused(
    const float* __restrict__ A, const float* __restrict__ B,
    const float* __restrict__ bias, const float* __restrict__ asrc,
    const float* __restrict__ adst, float* __restrict__ H,
    float* __restrict__ X, float* __restrict__ s_part,
    float* __restrict__ d_part, int N, int K)
{
    __shared__ float As[2][16][128];
    __shared__ float Bs[2][16][64];
    int t = threadIdx.x;
    int bm = blockIdx.y * 128, bn = blockIdx.x * 64;
    int tx = t & 15, ty = t >> 4;
    int ar = t >> 1, a8 = (t & 1) * 8;
    int bk = t >> 4, bc = (t & 15) * 4;
    const float* Aload = A + (size_t)(bm + ar) * K + a8;
    const float* Bload = B + (size_t)bk * N + bn + bc;
    unsigned bsB = sptr(Bs);

    float4 pa0 = *(const float4*)(Aload);
    float4 pa1 = *(const float4*)(Aload + 4);
    float4 pb  = *(const float4*)(Bload);

    ull acc[8][2];
#pragma unroll
    for (int i = 0; i < 8; i++) { acc[i][0] = 0ull; acc[i][1] = 0ull; }

    int NC = K >> 4;
    for (int ch = 0; ch < NC; ch++) {
        int p = ch & 1;
        As[p][a8 + 0][ar] = pa0.x; As[p][a8 + 1][ar] = pa0.y;
        As[p][a8 + 2][ar] = pa0.z; As[p][a8 + 3][ar] = pa0.w;
        As[p][a8 + 4][ar] = pa1.x; As[p][a8 + 5][ar] = pa1.y;
        As[p][a8 + 6][ar] = pa1.z; As[p][a8 + 7][ar] = pa1.w;
        *(float4*)&Bs[p][bk][bc] = pb;
        __syncthreads();
        if (ch + 1 < NC) {
            pa0 = *(const float4*)(Aload + (ch + 1) * 16);
            pa1 = *(const float4*)(Aload + (ch + 1) * 16 + 4);
            pb  = *(const float4*)(Bload + (size_t)(ch + 1) * 16 * N);
        }
        unsigned bbase = bsB + (unsigned)p * 4096u + (unsigned)tx * 16u;
#pragma unroll
        for (int k = 0; k < 16; k++) {
            float4 a0 = *(const float4*)&As[p][k][ty * 8];
            float4 a1 = *(const float4*)&As[p][k][ty * 8 + 4];
            ull b01, b23;
            lds2(b01, b23, bbase + (unsigned)k * 256u);
            ull d;
            d = dupf(a0.x); ffma2(acc[0][0], d, b01); ffma2(acc[0][1], d, b23);
            d = dupf(a0.y); ffma2(acc[1][0], d, b01); ffma2(acc[1][1], d, b23);
            d = dupf(a0.z); ffma2(acc[2][0], d, b01); ffma2(acc[2][1], d, b23);
            d = dupf(a0.w); ffma2(acc[3][0], d, b01); ffma2(acc[3][1], d, b23);
            d = dupf(a1.x); ffma2(acc[4][0], d, b01); ffma2(acc[4][1], d, b23);
            d = dupf(a1.y); ffma2(acc[5][0], d, b01); ffma2(acc[5][1], d, b23);
            d = dupf(a1.z); ffma2(acc[6][0], d, b01); ffma2(acc[6][1], d, b23);
            d = dupf(a1.w); ffma2(acc[7][0], d, b01); ffma2(acc[7][1], d, b23);
        }
    }

    float c[8][4];
#pragma unroll
    for (int rr = 0; rr < 8; rr++) {
        float2 lo = upk(acc[rr][0]);
        float2 hi = upk(acc[rr][1]);
        c[rr][0] = lo.x; c[rr][1] = lo.y; c[rr][2] = hi.x; c[rr][3] = hi.y;
    }
    int col = bn + tx * 4;

    if (bm >= 1024) {
        float4 bv = *(const float4*)&bias[col];
#pragma unroll
        for (int rr = 0; rr < 8; rr++) {
            float y0 = c[rr][0] + bv.x; y0 = y0 > 0.f ? y0 : 0.f;
            float y1 = c[rr][1] + bv.y; y1 = y1 > 0.f ? y1 : 0.f;
            float y2 = c[rr][2] + bv.z; y2 = y2 > 0.f ? y2 : 0.f;
            float y3 = c[rr][3] + bv.w; y3 = y3 > 0.f ? y3 : 0.f;
            *(float4*)&X[(size_t)(bm + ty * 8 + rr) * N + col] =
                make_float4(y0, y1, y2, y3);
        }
    } else {
        float4 av = *(const float4*)&asrc[col];
        float4 dv = *(const float4*)&adst[col];
        int NB = gridDim.x;
#pragma unroll
        for (int rr = 0; rr < 8; rr++) {
            *(float4*)&H[(size_t)(bm + ty * 8 + rr) * N + col] =
                make_float4(c[rr][0], c[rr][1], c[rr][2], c[rr][3]);
            float sp = c[rr][0] * av.x + c[rr][1] * av.y + c[rr][2] * av.z + c[rr][3] * av.w;
            float dp = c[rr][0] * dv.x + c[rr][1] * dv.y + c[rr][2] * dv.z + c[rr][3] * dv.w;
#pragma unroll
            for (int off = 8; off > 0; off >>= 1) {
                sp += __shfl_xor_sync(0xffffffffu, sp, off);
                dp += __shfl_xor_sync(0xffffffffu, dp, off);
            }
            if ((t & 15) == 0) {
                int row = bm + ty * 8 + rr;
                s_part[row * NB + blockIdx.x] = sp;
                d_part[row * NB + blockIdx.x] = dp;
            }
        }
    }
}

// ---------------- combine s/d partials; 4 blocks, each also emits a partial max(s) ----------------
template <int NB>
__global__ __launch_bounds__(256) void sd_combine(
    const float* __restrict__ s_part, const float* __restrict__ d_part)
{
    __shared__ float red[256];
    int t = threadIdx.x;
    int i = blockIdx.x * 256 + t;
    float s = 0.f, d = 0.f;
#pragma unroll
    for (int nb = 0; nb < NB; nb++) {
        s += s_part[i * NB + nb];
        d += d_part[i * NB + nb];
    }
    g_s[i] = s;
    g_d[i] = d;
    red[t] = s;
    __syncthreads();
    for (int o = 128; o > 0; o >>= 1) {
        if (t < o) red[t] = fmaxf(red[t], red[t + o]);
        __syncthreads();
    }
    if (t == 0) g_smaxp[blockIdx.x] = red[0];
}

// ---------------- attention partial: grid (128 j-blocks, 4 i-splits) ----------------
// exact softmax max via monotonicity: max_i leaky(s_i+d_j) = leaky(smax + d_j)
template <int D>
__global__ __launch_bounds__(256) void attn_partial(const float* __restrict__ h)
{
    __shared__ float buf[8192];
    __shared__ float mx_s[8], dv_s[8];
    __shared__ float smax_s;
    int t = threadIdx.x;
    int j0 = blockIdx.x * 8;
    int by = blockIdx.y;
    int i0 = by * 256;

    if (t < 8) dv_s[t] = g_d[j0 + t];
    if (t == 8)
        smax_s = fmaxf(fmaxf(g_smaxp[0], g_smaxp[1]), fmaxf(g_smaxp[2], g_smaxp[3]));
    __syncthreads();
    if (t < 8) {
        float e = smax_s + dv_s[t];
        mx_s[t] = e > 0.f ? e : 0.2f * e;
    }
    __syncthreads();

    // phase 1: w values for this i-range + partial denominators
    float* w_s = buf;              // [256][8]
    float* red = buf + 2048;       // [256][8]
    float si = g_s[i0 + t];
#pragma unroll
    for (int j = 0; j < 8; j++) {
        float e = si + dv_s[j];
        e = e > 0.f ? e : 0.2f * e;
        float wv = __expf(e - mx_s[j]);
        w_s[t * 8 + j] = wv;
        red[t * 8 + j] = wv;
    }
    __syncthreads();
    {
        int lane = t & 31, wj = t >> 5;
        float sval = 0.f;
        for (int r = lane; r < 256; r += 32) sval += red[r * 8 + wj];
#pragma unroll
        for (int o = 16; o > 0; o >>= 1)
            sval += __shfl_xor_sync(0xffffffffu, sval, o);
        if (lane == 0) g_psum[(j0 + wj) * 4 + by] = sval;
    }

    // phase 2: thread = 4 features, i-range split across IG groups
    const int FG = D / 4;
    const int IG = 256 / FG;
    const int ICNT = 256 / IG;
    int fg = t % FG, ig = t / FG;
    ull acc2[8][2];
#pragma unroll
    for (int j = 0; j < 8; j++) { acc2[j][0] = 0ull; acc2[j][1] = 0ull; }
    int ib = ig * ICNT;
#pragma unroll 4
    for (int ii = 0; ii < ICNT; ii++) {
        int il = ib + ii;
        ulonglong2 hv = *(const ulonglong2*)(h + (size_t)(i0 + il) * D + fg * 4);
        float4 w0 = *(const float4*)&w_s[il * 8];
        float4 w1 = *(const float4*)&w_s[il * 8 + 4];
        ull d;
        d = dupf(w0.x); ffma2(acc2[0][0], d, hv.x); ffma2(acc2[0][1], d, hv.y);
        d = dupf(w0.y); ffma2(acc2[1][0], d, hv.x); ffma2(acc2[1][1], d, hv.y);
        d = dupf(w0.z); ffma2(acc2[2][0], d, hv.x); ffma2(acc2[2][1], d, hv.y);
        d = dupf(w0.w); ffma2(acc2[3][0], d, hv.x); ffma2(acc2[3][1], d, hv.y);
        d = dupf(w1.x); ffma2(acc2[4][0], d, hv.x); ffma2(acc2[4][1], d, hv.y);
        d = dupf(w1.y); ffma2(acc2[5][0], d, hv.x); ffma2(acc2[5][1], d, hv.y);
        d = dupf(w1.z); ffma2(acc2[6][0], d, hv.x); ffma2(acc2[6][1], d, hv.y);
        d = dupf(w1.w); ffma2(acc2[7][0], d, hv.x); ffma2(acc2[7][1], d, hv.y);
    }
    __syncthreads();   // all reads of w_s done; reuse buf for group combine
#pragma unroll
    for (int j = 0; j < 8; j++) {
        float2 lo = upk(acc2[j][0]);
        float2 hi = upk(acc2[j][1]);
        *(float4*)&buf[(ig * 8 + j) * D + fg * 4] =
            make_float4(lo.x, lo.y, hi.x, hi.y);
    }
    __syncthreads();

    // combine IG groups, write partial output (unnormalized)
    // total output float4s = 8*D/4; with 256 threads -> K4 iterations
    const int K4 = (8 * D) / (4 * 256);   // 2 for D=256, 1 for D=128
#pragma unroll
    for (int k = 0; k < K4; k++) {
        int o4 = t + k * 256;
        int o = o4 * 4;
        int j = o / D, f = o % D;
        float4 sum = make_float4(0.f, 0.f, 0.f, 0.f);
#pragma unroll
        for (int g2 = 0; g2 < IG; g2++) {
            float4 vv = *(const float4*)&buf[(g2 * 8 + j) * D + f];
            sum.x += vv.x; sum.y += vv.y; sum.z += vv.z; sum.w += vv.w;
        }
        *(float4*)&g_apart[((size_t)by * 1024 + j0 + j) * D + f] = sum;
    }
}

// ---------------- attention finalize: sum 4 partials, normalize, +bias, relu ----------------
template <int D>
__global__ __launch_bounds__(256) void attn_final(
    const float* __restrict__ bias, float* __restrict__ out)
{
    int idx = blockIdx.x * 256 + threadIdx.x;   // float4 index, total 1024*D/4
    int e0 = idx * 4;
    int j = e0 / D, f = e0 % D;
    float4 ps = *(const float4*)&g_psum[j * 4];
    float inv = 1.0f / (ps.x + ps.y + ps.z + ps.w);
    float4 a = make_float4(0.f, 0.f, 0.f, 0.f);
#pragma unroll
    for (int p = 0; p < 4; p++) {
        float4 vv = *(const float4*)&g_apart[((size_t)p * 1024 + j) * D + f];
        a.x += vv.x; a.y += vv.y; a.z += vv.z; a.w += vv.w;
    }
    float4 bv = *(const float4*)&bias[f];
    float y0 = a.x * inv + bv.x; y0 = y0 > 0.f ? y0 : 0.f;
    float y1 = a.y * inv + bv.y; y1 = y1 > 0.f ? y1 : 0.f;
    float y2 = a.z * inv + bv.z; y2 = y2 > 0.f ? y2 : 0.f;
    float y3 = a.w * inv + bv.w; y3 = y3 > 0.f ? y3 : 0.f;
    *(float4*)&out[(size_t)j * D + f] = make_float4(y0, y1, y2, y3);
}

// ---------------- mean pool stage 1 ----------------
__global__ __launch_bounds__(128) void pool_partial_kernel()
{
    int b = blockIdx.x >> 3, ch = blockIdx.x & 7, t = threadIdx.x;
    const float* base = g_x2 + (b * 1024 + ch * 128) * 128;
    float acc = 0.f;
    for (int n = 0; n < 128; n++) acc += base[n * 128 + t];
    g_part[blockIdx.x * 128 + t] = acc;
}

// ---------------- stage 2: combine + linear + log_softmax ----------------
__global__ __launch_bounds__(128) void final_kernel(
    const float* __restrict__ W, const float* __restrict__ bo,
    float* __restrict__ out)
{
    __shared__ float meanv[128];
    __shared__ float logits[10];
    __shared__ float stats[2];
    int b = blockIdx.x;
    int t = threadIdx.x;
    float acc = 0.f;
#pragma unroll
    for (int k = 0; k < 8; k++) acc += g_part[(b * 8 + k) * 128 + t];
    meanv[t] = acc * (1.0f / 1024.0f);
    __syncthreads();
    if (t < 10) {
        float lg = bo[t];
        for (int f = 0; f < 128; f++) lg += meanv[f] * W[f * 10 + t];
        logits[t] = lg;
    }
    __syncthreads();
    if (t == 0) {
        float mv = -1e30f;
        for (int k = 0; k < 10; k++) mv = fmaxf(mv, logits[k]);
        float se = 0.f;
        for (int k = 0; k < 10; k++) se += expf(logits[k] - mv);
        stats[0] = mv;
        stats[1] = logf(se);
    }
    __syncthreads();
    if (t < 10) out[b * 10 + t] = logits[t] - stats[0] - stats[1];
}

// ---------------- launch ----------------
extern "C" void kernel_launch(void* const* d_in, const int* in_sizes, int n_in,
                              void* d_out, int out_size)
{
    const float* images  = (const float*)d_in[0];
    const float* conv1_w = (const float*)d_in[1];
    const float* conv1_b = (const float*)d_in[2];
    const float* bn1_g   = (const float*)d_in[3];
    const float* bn1_b   = (const float*)d_in[4];
    const float* bn1_m   = (const float*)d_in[5];
    const float* bn1_v   = (const float*)d_in[6];
    const float* conv2_w = (const float*)d_in[7];
    const float* conv2_b = (const float*)d_in[8];
    const float* bn2_g   = (const float*)d_in[9];
    const float* bn2_b   = (const float*)d_in[10];
    const float* bn2_m   = (const float*)d_in[11];
    const float* bn2_v   = (const float*)d_in[12];
    const float* gat1_w    = (const float*)d_in[13];
    const float* gat1_asrc = (const float*)d_in[14];
    const float* gat1_adst = (const float*)d_in[15];
    const float* gat1_bias = (const float*)d_in[16];
    const float* gat2_w    = (const float*)d_in[17];
    const float* gat2_asrc = (const float*)d_in[18];
    const float* gat2_adst = (const float*)d_in[19];
    const float* gat2_bias = (const float*)d_in[20];
    const float* out_w = (const float*)d_in[21];
    const float* out_b = (const float*)d_in[22];
    float* out = (float*)d_out;

    float* nodes0 = nullptr; cudaGetSymbolAddress((void**)&nodes0, g_nodes0);
    float* h1 = nullptr;     cudaGetSymbolAddress((void**)&h1, g_h1);
    float* x1 = nullptr;     cudaGetSymbolAddress((void**)&x1, g_x1);
    float* h2 = nullptr;     cudaGetSymbolAddress((void**)&h2, g_h2);
    float* x2 = nullptr;     cudaGetSymbolAddress((void**)&x2, g_x2);
    float* s1p = nullptr;    cudaGetSymbolAddress((void**)&s1p, g_s1p);
    float* d1p = nullptr;    cudaGetSymbolAddress((void**)&d1p, g_d1p);
    float* s2p = nullptr;    cudaGetSymbolAddress((void**)&s2p, g_s2p);
    float* d2p = nullptr;    cudaGetSymbolAddress((void**)&d2p, g_d2p);

    stage1_kernel<<<2048 + 288, 256>>>(images, conv1_w, conv1_b, bn1_g, bn1_b,
                                       bn1_m, bn1_v, conv2_w);
    conv2_kernel<<<dim3(16, 2, 8), 256>>>(conv2_b, bn2_g, bn2_b, bn2_m, bn2_v);

    // GAT layer 1
    sgemm_fused<<<dim3(4, 64), 256>>>(nodes0, gat1_w, gat1_bias, gat1_asrc,
                                      gat1_adst, h1, x1, s1p, d1p, 256, 128);
    sd_combine<4><<<4, 256>>>(s1p, d1p);
    attn_partial<256><<<dim3(128, 4), 256>>>(h1);
    attn_final<256><<<256, 256>>>(gat1_bias, x1);

    // GAT layer 2
    sgemm_fused<<<dim3(2, 64), 256>>>(x1, gat2_w, gat2_bias, gat2_asrc,
                                      gat2_adst, h2, x2, s2p, d2p, 128, 256);
    sd_combine<2><<<4, 256>>>(s2p, d2p);
    attn_partial<128><<<dim3(128, 4), 256>>>(h2);
    attn_final<128><<<128, 256>>>(gat2_bias, x2);

    pool_partial_kernel<<<64, 128>>>();
    final_kernel<<<8, 128>>>(out_w, out_b, out);
}